// round 11
// baseline (speedup 1.0000x reference)
#include <cuda_runtime.h>
#include <cuda_fp16.h>
#include <math.h>
#include <stdint.h>

#define HH 128
#define WW 128
#define BATCH 8
#define NPIX (BATCH*HH*WW)

__device__ float  g_cost[(size_t)NPIX*96];
__device__ __align__(16) __half g_bufA[(size_t)NPIX*128];
__device__ __align__(16) __half g_bufB[(size_t)NPIX*128];

__device__ __forceinline__ float mish_f(float v) {
    if (v > 20.f) return v;
    float u = __expf(v);
    float w = u * (u + 2.f);
    return v * __fdividef(w, w + 2.f);
}

__device__ __forceinline__ uint32_t f2tf32(float x) {
    uint32_t r;
    asm("cvt.rna.tf32.f32 %0, %1;" : "=r"(r) : "f"(x));
    return r;
}

__device__ __forceinline__ void mma_tf32(float acc[4],
                                         uint32_t a0, uint32_t a1, uint32_t a2, uint32_t a3,
                                         uint32_t b0, uint32_t b1) {
    asm volatile(
        "mma.sync.aligned.m16n8k8.row.col.f32.tf32.tf32.f32 "
        "{%0,%1,%2,%3}, {%4,%5,%6,%7}, {%8,%9}, {%0,%1,%2,%3};"
        : "+f"(acc[0]), "+f"(acc[1]), "+f"(acc[2]), "+f"(acc[3])
        : "r"(a0), "r"(a1), "r"(a2), "r"(a3), "r"(b0), "r"(b1));
}

__device__ __forceinline__ float4 ld_h4(const __half* p) {
    uint2 u = *(const uint2*)p;
    __half2 a = *reinterpret_cast<__half2*>(&u.x);
    __half2 b = *reinterpret_cast<__half2*>(&u.y);
    float2 fa = __half22float2(a);
    float2 fb = __half22float2(b);
    return make_float4(fa.x, fa.y, fb.x, fb.y);
}

// ================= cost volume =================
#define CCS 36
#define CRS 580
__global__ void __launch_bounds__(288, 2)
cost_kernel(const float* __restrict__ prv, const float* __restrict__ nxt,
            float* __restrict__ cost)
{
    extern __shared__ __align__(16) float sm[];
    const int b  = blockIdx.z;
    const int y0 = blockIdx.y * 16;
    const int xb = blockIdx.x * 8;
    const int tid = threadIdx.x;
    const int r  = tid / 18;
    const int q  = (tid % 18) / 9;
    const int di = tid % 9;
    const int xs = q * 4;

    float acc[36];
    #pragma unroll
    for (int k = 0; k < 36; k++) acc[k] = 0.f;

    for (int cc = 0; cc < 4; cc++) {
        if (cc) __syncthreads();
        for (int idx = tid; idx < 3072; idx += 288) {
            int c4 = idx & 7, col = (idx >> 3) & 15, row = idx >> 7;
            int gy = y0 - 4 + row, gx = xb - 4 + col;
            float4 v = make_float4(0.f,0.f,0.f,0.f);
            if (gy >= 0 && gy < HH && gx >= 0 && gx < WW)
                v = ((const float4*)nxt)[((b*HH+gy)*WW+gx)*32 + cc*8 + c4];
            *(float4*)(sm + row*CRS + col*CCS + c4*4) = v;
        }
        __syncthreads();

        const float* nbase = sm + (r + di)*CRS + xs*CCS;
        const float4* prow = (const float4*)prv + (size_t)((b*HH + y0 + r)*WW + xb + xs)*32 + cc*8;

        #pragma unroll 2
        for (int c4 = 0; c4 < 8; c4++) {
            float4 nv[12];
            #pragma unroll
            for (int m = 0; m < 12; m++)
                nv[m] = *(const float4*)(nbase + m*CCS + c4*4);
            #pragma unroll
            for (int i = 0; i < 4; i++) {
                float4 p = prow[i*32 + c4];
                #pragma unroll
                for (int dj = 0; dj < 9; dj++) {
                    float4 nn = nv[i + dj];
                    float s = acc[i*9+dj];
                    s = fmaf(p.x, nn.x, s); s = fmaf(p.y, nn.y, s);
                    s = fmaf(p.z, nn.z, s); s = fmaf(p.w, nn.w, s);
                    acc[i*9+dj] = s;
                }
            }
        }
    }

    const float inv = 1.0f / 128.0f;
    #pragma unroll
    for (int i = 0; i < 4; i++) {
        size_t base = (size_t)((b*HH + y0 + r)*WW + xb + xs + i)*96 + di*9;
        #pragma unroll
        for (int dj = 0; dj < 9; dj++)
            cost[base + dj] = acc[i*9+dj] * inv;
    }
}

// ================= fused sep-conv layer (mma.sync tf32, fp16 activations) =================
// HIN: fp16 input activations (stored pre-scaled by previous layer's oscale);
// bscale = 1/S_prev folded into B weights; oscale = S_cur applied after mish.
template<int CIN, int CINB, int COUT, bool L0M, bool HIN>
__global__ void __launch_bounds__(256, 2)
layer_mma(const void* __restrict__ inv_, const float* __restrict__ in2,
          const float* __restrict__ inc, const float* __restrict__ dww,
          const float* __restrict__ pw, const float* __restrict__ bias,
          __half* __restrict__ out, float bscale, float oscale)
{
    constexpr int KCH  = CINB / 32;
    constexpr int NT   = COUT / 8;
    constexpr int BSTP = 8*NT + 4;
    constexpr int BBUF = 32 * BSTP;
    constexpr int HBYT = HIN ? 14400 : 23040;
    constexpr int NSLOT = HIN ? 3 : 6;
    constexpr int NELEM = HIN ? 720 : 1440;
    constexpr int BQ = 256 / COUT, BR = 256 % COUT;

    extern __shared__ __align__(16) float smf[];
    char*     smc   = (char*)smf;
    float*    sdw   = smf;
    float*    sbias = smf + 288;
    uint32_t* dwt   = (uint32_t*)(smc + 1664 + 2*HBYT);
    uint32_t* Bsm   = (uint32_t*)(smc + 1664 + 2*HBYT + 18432);

    const int b  = blockIdx.z;
    const int ty = blockIdx.y * 16;
    const int tx = blockIdx.x * 8;
    const int tid = threadIdx.x;
    const int lane = tid & 31;
    const int wid  = tid >> 5;
    const int kq  = lane & 3;
    const int rr  = lane >> 2;
    const int pc4 = tid & 7;

    if (tid < COUT) sbias[tid] = bias[tid];

    int      hoff[NSLOT];
    int      hsz [NSLOT];
    uint32_t hdst[NSLOT];
    const uint32_t halo_sa = (uint32_t)__cvta_generic_to_shared(smc + 1664);
    #pragma unroll
    for (int s = 0; s < NSLOT; s++) {
        int idx = tid + s*256;
        int p = HIN ? (idx >> 2) : (idx >> 3);
        int hy = p / 10, hx = p - hy*10;
        int gy = ty - 1 + hy, gx = tx - 1 + hx;
        bool v = (idx < NELEM) && gy >= 0 && gy < HH && gx >= 0 && gx < WW;
        int gyc = min(max(gy, 0), HH-1), gxc = min(max(gx, 0), WW-1);
        hoff[s] = (b*HH + gyc)*WW + gxc;
        hsz [s] = v ? 16 : 0;
        hdst[s] = halo_sa + (HIN ? ((uint32_t)p*80 + (uint32_t)(idx & 3)*16)
                                 : ((uint32_t)p*128 + (uint32_t)(idx & 7)*16));
    }

    auto issue_prefetch = [&](int kn, uint32_t bufb) {
        if constexpr (HIN) {
            const char* base = (const char*)inv_;
            #pragma unroll
            for (int s = 0; s < 3; s++) {
                int idx = tid + s*256;
                if (idx < 720) {
                    const void* p = base + ((size_t)hoff[s]*CINB + kn*32)*2
                                         + (size_t)(idx & 3)*16;
                    asm volatile("cp.async.cg.shared.global [%0], [%1], 16, %2;"
                                 :: "r"(hdst[s] + bufb), "l"(p), "r"(hsz[s]) : "memory");
                }
            }
        } else {
            const float4* src; int cof, strd;
            if constexpr (L0M) {
                if (kn < 4)      { src = (const float4*)inv_; cof = kn*8;     strd = 32; }
                else if (kn < 8) { src = (const float4*)in2;  cof = (kn-4)*8; strd = 32; }
                else             { src = (const float4*)inc;  cof = (kn-8)*8; strd = 24; }
            } else {
                src = (const float4*)inv_; cof = kn*8; strd = CINB/4;
            }
            #pragma unroll
            for (int s = 0; s < 6; s++) {
                if (tid + s*256 < 1440) {
                    const void* p = (const void*)(src + (size_t)hoff[s]*strd + cof + pc4);
                    asm volatile("cp.async.cg.shared.global [%0], [%1], 16, %2;"
                                 :: "r"(hdst[s] + bufb), "l"(p), "r"(hsz[s]) : "memory");
                }
            }
        }
        asm volatile("cp.async.commit_group;" ::: "memory");
    };

    float acc[NT][4];
    #pragma unroll
    for (int n = 0; n < NT; n++)
        #pragma unroll
        for (int j = 0; j < 4; j++) acc[n][j] = 0.f;

    issue_prefetch(0, 0);

    const int dr  = tid >> 4;
    const int dxh = ((tid >> 3) & 1) * 4;
    const int kk0 = tid / COUT, co0 = tid - (tid / COUT)*COUT;

    for (int kc = 0; kc < KCH; kc++) {
        const int k0 = kc * 32;
        uint32_t* Bb = Bsm + (kc & 1) * BBUF;

        if (kc + 1 < KCH)
            issue_prefetch(kc + 1, (uint32_t)(((kc + 1) & 1) * HBYT));

        // ---- B chunk [32][COUT] -> permuted tf32 smem (scaled by bscale) ----
        {
            int kk = kk0, co = co0;
            #pragma unroll
            for (int s = 0; s < COUT/8; s++) {
                int cb = k0 + kk;
                int corig = L0M ? (cb < 256 ? cb + 81 : cb - 256) : cb;
                bool valid = L0M ? (cb < 337) : true;
                float w = valid ? pw[(size_t)corig*COUT + co] * bscale : 0.f;
                Bb[kk*BSTP + (co & 7)*NT + (co >> 3)] = f2tf32(w);
                co += BR; kk += BQ;
                if (co >= COUT) { co -= COUT; kk++; }
            }
        }
        // ---- depthwise weights chunk [9][32] ----
        #pragma unroll
        for (int s = 0; s < 2; s++) {
            int j = tid + s*256;
            if (j < 288) {
                int t = j >> 5, c = j & 31;
                int cb = k0 + c;
                int corig = L0M ? (cb < 256 ? cb + 81 : cb - 256) : cb;
                bool valid = L0M ? (cb < 337) : true;
                sdw[j] = valid ? dww[t*CIN + corig] : 0.f;
            }
        }
        if (kc + 1 < KCH) asm volatile("cp.async.wait_group 1;" ::: "memory");
        else              asm volatile("cp.async.wait_group 0;" ::: "memory");
        __syncthreads();   // [A]

        // ---- depthwise 3x3 ----
        {
            float4 o0 = make_float4(0.f,0.f,0.f,0.f);
            float4 o1 = o0, o2 = o0, o3 = o0;
            #pragma unroll
            for (int tyy = 0; tyy < 3; tyy++) {
                float4 h0, h1, h2, h3, h4, h5;
                if constexpr (HIN) {
                    const __half* hb = (const __half*)(smc + 1664) + (kc & 1)*7200;
                    const __half* hr = hb + ((dr + tyy)*10 + dxh)*40 + pc4*4;
                    h0 = ld_h4(hr + 0*40); h1 = ld_h4(hr + 1*40);
                    h2 = ld_h4(hr + 2*40); h3 = ld_h4(hr + 3*40);
                    h4 = ld_h4(hr + 4*40); h5 = ld_h4(hr + 5*40);
                } else {
                    const float* hb = (const float*)(smc + 1664) + (kc & 1)*5760;
                    const float* hr = hb + ((dr + tyy)*10 + dxh)*32 + pc4*4;
                    h0 = *(const float4*)(hr + 0*32); h1 = *(const float4*)(hr + 1*32);
                    h2 = *(const float4*)(hr + 2*32); h3 = *(const float4*)(hr + 3*32);
                    h4 = *(const float4*)(hr + 4*32); h5 = *(const float4*)(hr + 5*32);
                }
                float4 w0 = *(const float4*)(sdw + (tyy*3+0)*32 + pc4*4);
                float4 w1 = *(const float4*)(sdw + (tyy*3+1)*32 + pc4*4);
                float4 w2 = *(const float4*)(sdw + (tyy*3+2)*32 + pc4*4);
                #define DWACC(o, a, b, c) \
                    o.x = fmaf(w0.x, a.x, o.x); o.y = fmaf(w0.y, a.y, o.y); \
                    o.z = fmaf(w0.z, a.z, o.z); o.w = fmaf(w0.w, a.w, o.w); \
                    o.x = fmaf(w1.x, b.x, o.x); o.y = fmaf(w1.y, b.y, o.y); \
                    o.z = fmaf(w1.z, b.z, o.z); o.w = fmaf(w1.w, b.w, o.w); \
                    o.x = fmaf(w2.x, c.x, o.x); o.y = fmaf(w2.y, c.y, o.y); \
                    o.z = fmaf(w2.z, c.z, o.z); o.w = fmaf(w2.w, c.w, o.w);
                DWACC(o0, h0, h1, h2)
                DWACC(o1, h1, h2, h3)
                DWACC(o2, h2, h3, h4)
                DWACC(o3, h3, h4, h5)
                #undef DWACC
            }
            const int pxb = dr*8 + dxh;
            uint4 t0, t1, t2, t3;
            t0.x=f2tf32(o0.x); t0.y=f2tf32(o0.y); t0.z=f2tf32(o0.z); t0.w=f2tf32(o0.w);
            t1.x=f2tf32(o1.x); t1.y=f2tf32(o1.y); t1.z=f2tf32(o1.z); t1.w=f2tf32(o1.w);
            t2.x=f2tf32(o2.x); t2.y=f2tf32(o2.y); t2.z=f2tf32(o2.z); t2.w=f2tf32(o2.w);
            t3.x=f2tf32(o3.x); t3.y=f2tf32(o3.y); t3.z=f2tf32(o3.z); t3.w=f2tf32(o3.w);
            *(uint4*)(dwt + (pxb+0)*36 + pc4*4) = t0;
            *(uint4*)(dwt + (pxb+1)*36 + pc4*4) = t1;
            *(uint4*)(dwt + (pxb+2)*36 + pc4*4) = t2;
            *(uint4*)(dwt + (pxb+3)*36 + pc4*4) = t3;
        }
        __syncthreads();   // [B]

        // ---- MMA ----
        const uint32_t* arow0 = dwt + (wid*16 + rr)*36;
        const uint32_t* arow1 = arow0 + 8*36;
        #pragma unroll
        for (int kb = 0; kb < 4; kb++) {
            const int kof = kb*8 + kq;
            uint32_t a0 = arow0[kof];
            uint32_t a1 = arow1[kof];
            uint32_t a2 = arow0[kof + 4];
            uint32_t a3 = arow1[kof + 4];
            const uint4* b0p = (const uint4*)(Bb + kof*BSTP + rr*NT);
            const uint4* b1p = (const uint4*)(Bb + (kof+4)*BSTP + rr*NT);
            #pragma unroll
            for (int ng = 0; ng < NT/4; ng++) {
                uint4 b0 = b0p[ng];
                uint4 b1 = b1p[ng];
                mma_tf32(acc[ng*4+0], a0,a1,a2,a3, b0.x, b1.x);
                mma_tf32(acc[ng*4+1], a0,a1,a2,a3, b0.y, b1.y);
                mma_tf32(acc[ng*4+2], a0,a1,a2,a3, b0.z, b1.z);
                mma_tf32(acc[ng*4+3], a0,a1,a2,a3, b0.w, b1.w);
            }
        }
    }

    // ---- epilogue: bias + mish, scale, half2 stores ----
    const int px0 = wid*16 + rr;
    const int px1 = px0 + 8;
    const int y0 = ty + (px0 >> 3), x0c = tx + (px0 & 7);
    const int y1 = ty + (px1 >> 3), x1c = tx + (px1 & 7);
    __half* op0 = out + (size_t)((b*HH + y0)*WW + x0c)*COUT;
    __half* op1 = out + (size_t)((b*HH + y1)*WW + x1c)*COUT;

    #pragma unroll
    for (int nt = 0; nt < NT; nt++) {
        int ch = nt*8 + kq*2;
        float bb0 = sbias[ch], bb1 = sbias[ch+1];
        *(__half2*)(op0 + ch) = __floats2half2_rn(mish_f(acc[nt][0] + bb0) * oscale,
                                                  mish_f(acc[nt][1] + bb1) * oscale);
        *(__half2*)(op1 + ch) = __floats2half2_rn(mish_f(acc[nt][2] + bb0) * oscale,
                                                  mish_f(acc[nt][3] + bb1) * oscale);
    }
}

// ================= final flow head (32 -> 2, half in, float out) =================
__global__ void layer5_kernel(const __half* __restrict__ in,
                              const float* __restrict__ dww,
                              const float* __restrict__ pw,
                              float* __restrict__ out, float iscale)
{
    __shared__ __align__(16) float halo[180*36];
    __shared__ __align__(16) float wsm[288 + 64];

    const int b  = blockIdx.z;
    const int ty = blockIdx.y * 16;
    const int tx = blockIdx.x * 8;
    const int tid = threadIdx.x;

    for (int j = tid; j < 288; j += 128) wsm[j] = dww[j] * iscale;
    if (tid < 64) wsm[288 + tid] = pw[tid];

    for (int idx = tid; idx < 720; idx += 128) {
        int g8 = idx & 3, p = idx >> 2;
        int hy = p / 10, hx = p - hy*10;
        int gy = ty - 1 + hy, gx = tx - 1 + hx;
        uint4 v = make_uint4(0u,0u,0u,0u);
        if (gy >= 0 && gy < HH && gx >= 0 && gx < WW)
            v = ((const uint4*)in)[(size_t)((b*HH+gy)*WW+gx)*4 + g8];
        __half2* hp = (__half2*)&v;
        float2 f0 = __half22float2(hp[0]), f1 = __half22float2(hp[1]);
        float2 f2 = __half22float2(hp[2]), f3 = __half22float2(hp[3]);
        *(float4*)(halo + p*36 + g8*8)     = make_float4(f0.x, f0.y, f1.x, f1.y);
        *(float4*)(halo + p*36 + g8*8 + 4) = make_float4(f2.x, f2.y, f3.x, f3.y);
    }
    __syncthreads();

    int y = tid >> 3, x = tid & 7;
    float dwv[32];
    #pragma unroll
    for (int c = 0; c < 32; c++) dwv[c] = 0.f;

    #pragma unroll
    for (int t = 0; t < 9; t++) {
        int hp = ((y + t/3)*10 + (x + t%3))*36;
        #pragma unroll
        for (int c4 = 0; c4 < 8; c4++) {
            float4 h = *(const float4*)(halo + hp + c4*4);
            float4 w = *(const float4*)(wsm + t*32 + c4*4);
            dwv[c4*4+0] = fmaf(w.x, h.x, dwv[c4*4+0]);
            dwv[c4*4+1] = fmaf(w.y, h.y, dwv[c4*4+1]);
            dwv[c4*4+2] = fmaf(w.z, h.z, dwv[c4*4+2]);
            dwv[c4*4+3] = fmaf(w.w, h.w, dwv[c4*4+3]);
        }
    }

    float o0 = 0.f, o1 = 0.f;
    #pragma unroll
    for (int c = 0; c < 32; c++) {
        o0 = fmaf(dwv[c], wsm[288 + c*2 + 0], o0);
        o1 = fmaf(dwv[c], wsm[288 + c*2 + 1], o1);
    }
    int pix = (b*HH + ty + y)*WW + tx + x;
    float2 r; r.x = o0; r.y = o1;
    *(float2*)(out + (size_t)pix*2) = r;
}

// ================= host launch =================
extern "C" void kernel_launch(void* const* d_in, const int* in_sizes, int n_in,
                              void* d_out, int out_size)
{
    const float* prv = (const float*)d_in[0];
    const float* nxt = (const float*)d_in[1];
    const float* dw0 = (const float*)d_in[2];
    const float* pw0 = (const float*)d_in[3];
    const float* b0  = (const float*)d_in[4];
    const float* dw1 = (const float*)d_in[5];
    const float* pw1 = (const float*)d_in[6];
    const float* b1  = (const float*)d_in[7];
    const float* dw2 = (const float*)d_in[8];
    const float* pw2 = (const float*)d_in[9];
    const float* b2  = (const float*)d_in[10];
    const float* dw3 = (const float*)d_in[11];
    const float* pw3 = (const float*)d_in[12];
    const float* b3  = (const float*)d_in[13];
    const float* dw4 = (const float*)d_in[14];
    const float* pw4 = (const float*)d_in[15];
    const float* b4  = (const float*)d_in[16];
    const float* dw5 = (const float*)d_in[17];
    const float* pw5 = (const float*)d_in[18];
    float* out = (float*)d_out;

    float *cost; __half *bufA, *bufB;
    cudaGetSymbolAddress((void**)&cost, g_cost);
    cudaGetSymbolAddress((void**)&bufA, g_bufA);
    cudaGetSymbolAddress((void**)&bufB, g_bufB);

    // per-layer-output fp16 storage scales (powers of two; exact in fp)
    const float S0 = 8.f, S1 = 128.f, S2 = 2048.f, S3 = 32768.f, S4 = 524288.f;

    const int SC = 24*CRS*4;
    const int SL0 = 1664 + 46080 + 18432 + 33792;  // 99968
    const int SL1 = 1664 + 28800 + 18432 + 33792;  // 82688
    const int SL2 = 1664 + 28800 + 18432 + 25600;  // 74496
    const int SL3 = 1664 + 28800 + 18432 + 17408;  // 66304
    const int SL4 = 1664 + 28800 + 18432 + 9216;   // 58112

    cudaFuncSetAttribute(cost_kernel, cudaFuncAttributeMaxDynamicSharedMemorySize, SC);
    cudaFuncSetAttribute((const void*)layer_mma<337,352,128,true ,false>, cudaFuncAttributeMaxDynamicSharedMemorySize, SL0);
    cudaFuncSetAttribute((const void*)layer_mma<128,128,128,false,true >, cudaFuncAttributeMaxDynamicSharedMemorySize, SL1);
    cudaFuncSetAttribute((const void*)layer_mma<128,128, 96,false,true >, cudaFuncAttributeMaxDynamicSharedMemorySize, SL2);
    cudaFuncSetAttribute((const void*)layer_mma< 96, 96, 64,false,true >, cudaFuncAttributeMaxDynamicSharedMemorySize, SL3);
    cudaFuncSetAttribute((const void*)layer_mma< 64, 64, 32,false,true >, cudaFuncAttributeMaxDynamicSharedMemorySize, SL4);

    dim3 cgrid(16, 8, BATCH);
    cost_kernel<<<cgrid, 288, SC>>>(prv, nxt, cost);

    dim3 lgrid(16, 8, BATCH);
    layer_mma<337,352,128,true ,false><<<lgrid, 256, SL0>>>(prv,  nxt, cost, dw0, pw0, b0, bufA, 1.0f,    S0);
    layer_mma<128,128,128,false,true ><<<lgrid, 256, SL1>>>(bufA, nullptr, nullptr, dw1, pw1, b1, bufB, 1.f/S0, S1);
    layer_mma<128,128, 96,false,true ><<<lgrid, 256, SL2>>>(bufB, nullptr, nullptr, dw2, pw2, b2, bufA, 1.f/S1, S2);
    layer_mma< 96, 96, 64,false,true ><<<lgrid, 256, SL3>>>(bufA, nullptr, nullptr, dw3, pw3, b3, bufB, 1.f/S2, S3);
    layer_mma< 64, 64, 32,false,true ><<<lgrid, 256, SL4>>>(bufB, nullptr, nullptr, dw4, pw4, b4, bufA, 1.f/S3, S4);

    layer5_kernel<<<lgrid, 128>>>(bufA, dw5, pw5, out, 1.f/S4);
}

// round 12
// speedup vs baseline: 1.0266x; 1.0266x over previous
#include <cuda_runtime.h>
#include <cuda_fp16.h>
#include <math.h>
#include <stdint.h>

#define HH 128
#define WW 128
#define BATCH 8
#define NPIX (BATCH*HH*WW)

__device__ float  g_cost[(size_t)NPIX*96];
__device__ __align__(16) __half g_bufA[(size_t)NPIX*128];
__device__ __align__(16) __half g_bufB[(size_t)NPIX*128];

__device__ __forceinline__ float mish_f(float v) {
    if (v > 20.f) return v;
    float u = __expf(v);
    float w = u * (u + 2.f);
    return v * __fdividef(w, w + 2.f);
}

__device__ __forceinline__ uint32_t f2tf32(float x) {
    uint32_t r;
    asm("cvt.rna.tf32.f32 %0, %1;" : "=r"(r) : "f"(x));
    return r;
}

__device__ __forceinline__ void mma_tf32(float acc[4],
                                         uint32_t a0, uint32_t a1, uint32_t a2, uint32_t a3,
                                         uint32_t b0, uint32_t b1) {
    asm volatile(
        "mma.sync.aligned.m16n8k8.row.col.f32.tf32.tf32.f32 "
        "{%0,%1,%2,%3}, {%4,%5,%6,%7}, {%8,%9}, {%0,%1,%2,%3};"
        : "+f"(acc[0]), "+f"(acc[1]), "+f"(acc[2]), "+f"(acc[3])
        : "r"(a0), "r"(a1), "r"(a2), "r"(a3), "r"(b0), "r"(b1));
}

__device__ __forceinline__ float4 ld_h4(const __half* p) {
    uint2 u = *(const uint2*)p;
    __half2 a = *reinterpret_cast<__half2*>(&u.x);
    __half2 b = *reinterpret_cast<__half2*>(&u.y);
    float2 fa = __half22float2(a);
    float2 fb = __half22float2(b);
    return make_float4(fa.x, fa.y, fb.x, fb.y);
}

// ================= cost volume =================
#define CCS 36
#define CRS 580
__global__ void __launch_bounds__(288, 2)
cost_kernel(const float* __restrict__ prv, const float* __restrict__ nxt,
            float* __restrict__ cost)
{
    extern __shared__ __align__(16) float sm[];
    const int b  = blockIdx.z;
    const int y0 = blockIdx.y * 16;
    const int xb = blockIdx.x * 8;
    const int tid = threadIdx.x;
    const int r  = tid / 18;
    const int q  = (tid % 18) / 9;
    const int di = tid % 9;
    const int xs = q * 4;

    float acc[36];
    #pragma unroll
    for (int k = 0; k < 36; k++) acc[k] = 0.f;

    for (int cc = 0; cc < 4; cc++) {
        if (cc) __syncthreads();
        for (int idx = tid; idx < 3072; idx += 288) {
            int c4 = idx & 7, col = (idx >> 3) & 15, row = idx >> 7;
            int gy = y0 - 4 + row, gx = xb - 4 + col;
            float4 v = make_float4(0.f,0.f,0.f,0.f);
            if (gy >= 0 && gy < HH && gx >= 0 && gx < WW)
                v = ((const float4*)nxt)[((b*HH+gy)*WW+gx)*32 + cc*8 + c4];
            *(float4*)(sm + row*CRS + col*CCS + c4*4) = v;
        }
        __syncthreads();

        const float* nbase = sm + (r + di)*CRS + xs*CCS;
        const float4* prow = (const float4*)prv + (size_t)((b*HH + y0 + r)*WW + xb + xs)*32 + cc*8;

        #pragma unroll 2
        for (int c4 = 0; c4 < 8; c4++) {
            float4 nv[12];
            #pragma unroll
            for (int m = 0; m < 12; m++)
                nv[m] = *(const float4*)(nbase + m*CCS + c4*4);
            #pragma unroll
            for (int i = 0; i < 4; i++) {
                float4 p = prow[i*32 + c4];
                #pragma unroll
                for (int dj = 0; dj < 9; dj++) {
                    float4 nn = nv[i + dj];
                    float s = acc[i*9+dj];
                    s = fmaf(p.x, nn.x, s); s = fmaf(p.y, nn.y, s);
                    s = fmaf(p.z, nn.z, s); s = fmaf(p.w, nn.w, s);
                    acc[i*9+dj] = s;
                }
            }
        }
    }

    const float inv = 1.0f / 128.0f;
    #pragma unroll
    for (int i = 0; i < 4; i++) {
        size_t base = (size_t)((b*HH + y0 + r)*WW + xb + xs + i)*96 + di*9;
        #pragma unroll
        for (int dj = 0; dj < 9; dj++)
            cost[base + dj] = acc[i*9+dj] * inv;
    }
}

// ================= fused sep-conv layer (mma.sync tf32, warp-pipelined) =================
// ONE block barrier per chunk: depthwise->MMA handoff is intra-warp (warp w's
// depthwise writes exactly dwt rows 16w..16w+15, which only warp w's MMA reads),
// so the second barrier is __syncwarp(). sdw double-buffered; halo prefetch for
// kc+1 issued after depthwise (never collides with straggler readers of kc's buf).
template<int CIN, int CINB, int COUT, bool L0M, bool HIN>
__global__ void __launch_bounds__(256, 2)
layer_mma(const void* __restrict__ inv_, const float* __restrict__ in2,
          const float* __restrict__ inc, const float* __restrict__ dww,
          const float* __restrict__ pw, const float* __restrict__ bias,
          __half* __restrict__ out, float bscale, float oscale)
{
    constexpr int KCH  = CINB / 32;
    constexpr int NT   = COUT / 8;
    constexpr int BSTP = 8*NT + 4;
    constexpr int BBUF = 32 * BSTP;
    constexpr int HBYT = HIN ? 14400 : 23040;
    constexpr int NSLOT = HIN ? 3 : 6;
    constexpr int NELEM = HIN ? 720 : 1440;
    constexpr int BQ = 256 / COUT, BR = 256 % COUT;

    extern __shared__ __align__(16) float smf[];
    char*     smc   = (char*)smf;
    float*    sdw   = smf;                              // 2 x 288
    float*    sbias = smf + 576;                        // 128 (+pad)
    // halo at byte 2816, double-buffered
    uint32_t* dwt   = (uint32_t*)(smc + 2816 + 2*HBYT);
    uint32_t* Bsm   = (uint32_t*)(smc + 2816 + 2*HBYT + 18432);

    const int b  = blockIdx.z;
    const int ty = blockIdx.y * 16;
    const int tx = blockIdx.x * 8;
    const int tid = threadIdx.x;
    const int lane = tid & 31;
    const int wid  = tid >> 5;
    const int kq  = lane & 3;
    const int rr  = lane >> 2;
    const int pc4 = tid & 7;

    if (tid < COUT) sbias[tid] = bias[tid];

    int      hoff[NSLOT];
    int      hsz [NSLOT];
    uint32_t hdst[NSLOT];
    const uint32_t halo_sa = (uint32_t)__cvta_generic_to_shared(smc + 2816);
    #pragma unroll
    for (int s = 0; s < NSLOT; s++) {
        int idx = tid + s*256;
        int p = HIN ? (idx >> 2) : (idx >> 3);
        int hy = p / 10, hx = p - hy*10;
        int gy = ty - 1 + hy, gx = tx - 1 + hx;
        bool v = (idx < NELEM) && gy >= 0 && gy < HH && gx >= 0 && gx < WW;
        int gyc = min(max(gy, 0), HH-1), gxc = min(max(gx, 0), WW-1);
        hoff[s] = (b*HH + gyc)*WW + gxc;
        hsz [s] = v ? 16 : 0;
        hdst[s] = halo_sa + (HIN ? ((uint32_t)p*80 + (uint32_t)(idx & 3)*16)
                                 : ((uint32_t)p*128 + (uint32_t)(idx & 7)*16));
    }

    auto issue_prefetch = [&](int kn, uint32_t bufb) {
        if constexpr (HIN) {
            const char* base = (const char*)inv_;
            #pragma unroll
            for (int s = 0; s < 3; s++) {
                int idx = tid + s*256;
                if (idx < 720) {
                    const void* p = base + ((size_t)hoff[s]*CINB + kn*32)*2
                                         + (size_t)(idx & 3)*16;
                    asm volatile("cp.async.cg.shared.global [%0], [%1], 16, %2;"
                                 :: "r"(hdst[s] + bufb), "l"(p), "r"(hsz[s]) : "memory");
                }
            }
        } else {
            const float4* src; int cof, strd;
            if constexpr (L0M) {
                if (kn < 4)      { src = (const float4*)inv_; cof = kn*8;     strd = 32; }
                else if (kn < 8) { src = (const float4*)in2;  cof = (kn-4)*8; strd = 32; }
                else             { src = (const float4*)inc;  cof = (kn-8)*8; strd = 24; }
            } else {
                src = (const float4*)inv_; cof = kn*8; strd = CINB/4;
            }
            #pragma unroll
            for (int s = 0; s < 6; s++) {
                if (tid + s*256 < 1440) {
                    const void* p = (const void*)(src + (size_t)hoff[s]*strd + cof + pc4);
                    asm volatile("cp.async.cg.shared.global [%0], [%1], 16, %2;"
                                 :: "r"(hdst[s] + bufb), "l"(p), "r"(hsz[s]) : "memory");
                }
            }
        }
        asm volatile("cp.async.commit_group;" ::: "memory");
    };

    float acc[NT][4];
    #pragma unroll
    for (int n = 0; n < NT; n++)
        #pragma unroll
        for (int j = 0; j < 4; j++) acc[n][j] = 0.f;

    issue_prefetch(0, 0);

    const int dr  = tid >> 4;
    const int dxh = ((tid >> 3) & 1) * 4;
    const int kk0 = tid / COUT, co0 = tid - (tid / COUT)*COUT;

    for (int kc = 0; kc < KCH; kc++) {
        const int k0 = kc * 32;
        uint32_t* Bb = Bsm + (kc & 1) * BBUF;
        float* sdwb  = sdw + (kc & 1) * 288;

        // ---- B chunk [32][COUT] -> permuted tf32 smem (scaled by bscale) ----
        {
            int kk = kk0, co = co0;
            #pragma unroll
            for (int s = 0; s < COUT/8; s++) {
                int cb = k0 + kk;
                int corig = L0M ? (cb < 256 ? cb + 81 : cb - 256) : cb;
                bool valid = L0M ? (cb < 337) : true;
                float w = valid ? pw[(size_t)corig*COUT + co] * bscale : 0.f;
                Bb[kk*BSTP + (co & 7)*NT + (co >> 3)] = f2tf32(w);
                co += BR; kk += BQ;
                if (co >= COUT) { co -= COUT; kk++; }
            }
        }
        // ---- depthwise weights chunk [9][32] (double-buffered) ----
        #pragma unroll
        for (int s = 0; s < 2; s++) {
            int j = tid + s*256;
            if (j < 288) {
                int t = j >> 5, c = j & 31;
                int cb = k0 + c;
                int corig = L0M ? (cb < 256 ? cb + 81 : cb - 256) : cb;
                bool valid = L0M ? (cb < 337) : true;
                sdwb[j] = valid ? dww[t*CIN + corig] : 0.f;
            }
        }
        asm volatile("cp.async.wait_group 0;" ::: "memory");
        __syncthreads();   // [A] the ONLY block barrier per chunk

        // ---- depthwise 3x3: 4 adjacent px, one c4 quad, row-window reuse ----
        {
            float4 o0 = make_float4(0.f,0.f,0.f,0.f);
            float4 o1 = o0, o2 = o0, o3 = o0;
            #pragma unroll
            for (int tyy = 0; tyy < 3; tyy++) {
                float4 h0, h1, h2, h3, h4, h5;
                if constexpr (HIN) {
                    const __half* hb = (const __half*)(smc + 2816) + (kc & 1)*7200;
                    const __half* hr = hb + ((dr + tyy)*10 + dxh)*40 + pc4*4;
                    h0 = ld_h4(hr + 0*40); h1 = ld_h4(hr + 1*40);
                    h2 = ld_h4(hr + 2*40); h3 = ld_h4(hr + 3*40);
                    h4 = ld_h4(hr + 4*40); h5 = ld_h4(hr + 5*40);
                } else {
                    const float* hb = (const float*)(smc + 2816) + (kc & 1)*5760;
                    const float* hr = hb + ((dr + tyy)*10 + dxh)*32 + pc4*4;
                    h0 = *(const float4*)(hr + 0*32); h1 = *(const float4*)(hr + 1*32);
                    h2 = *(const float4*)(hr + 2*32); h3 = *(const float4*)(hr + 3*32);
                    h4 = *(const float4*)(hr + 4*32); h5 = *(const float4*)(hr + 5*32);
                }
                float4 w0 = *(const float4*)(sdwb + (tyy*3+0)*32 + pc4*4);
                float4 w1 = *(const float4*)(sdwb + (tyy*3+1)*32 + pc4*4);
                float4 w2 = *(const float4*)(sdwb + (tyy*3+2)*32 + pc4*4);
                #define DWACC(o, a, b, c) \
                    o.x = fmaf(w0.x, a.x, o.x); o.y = fmaf(w0.y, a.y, o.y); \
                    o.z = fmaf(w0.z, a.z, o.z); o.w = fmaf(w0.w, a.w, o.w); \
                    o.x = fmaf(w1.x, b.x, o.x); o.y = fmaf(w1.y, b.y, o.y); \
                    o.z = fmaf(w1.z, b.z, o.z); o.w = fmaf(w1.w, b.w, o.w); \
                    o.x = fmaf(w2.x, c.x, o.x); o.y = fmaf(w2.y, c.y, o.y); \
                    o.z = fmaf(w2.z, c.z, o.z); o.w = fmaf(w2.w, c.w, o.w);
                DWACC(o0, h0, h1, h2)
                DWACC(o1, h1, h2, h3)
                DWACC(o2, h2, h3, h4)
                DWACC(o3, h3, h4, h5)
                #undef DWACC
            }
            const int pxb = dr*8 + dxh;
            uint4 t0, t1, t2, t3;
            t0.x=f2tf32(o0.x); t0.y=f2tf32(o0.y); t0.z=f2tf32(o0.z); t0.w=f2tf32(o0.w);
            t1.x=f2tf32(o1.x); t1.y=f2tf32(o1.y); t1.z=f2tf32(o1.z); t1.w=f2tf32(o1.w);
            t2.x=f2tf32(o2.x); t2.y=f2tf32(o2.y); t2.z=f2tf32(o2.z); t2.w=f2tf32(o2.w);
            t3.x=f2tf32(o3.x); t3.y=f2tf32(o3.y); t3.z=f2tf32(o3.z); t3.w=f2tf32(o3.w);
            *(uint4*)(dwt + (pxb+0)*36 + pc4*4) = t0;
            *(uint4*)(dwt + (pxb+1)*36 + pc4*4) = t1;
            *(uint4*)(dwt + (pxb+2)*36 + pc4*4) = t2;
            *(uint4*)(dwt + (pxb+3)*36 + pc4*4) = t3;
        }

        // ---- prefetch halo for chunk kc+1 (safe: stragglers read other buffer) ----
        if (kc + 1 < KCH)
            issue_prefetch(kc + 1, (uint32_t)(((kc + 1) & 1) * HBYT));

        __syncwarp();      // [B] intra-warp handoff: dwt rows 16w..16w+15

        // ---- MMA: 4 k-blocks of 8, B fragments via LDS.128 ----
        const uint32_t* arow0 = dwt + (wid*16 + rr)*36;
        const uint32_t* arow1 = arow0 + 8*36;
        #pragma unroll
        for (int kb = 0; kb < 4; kb++) {
            const int kof = kb*8 + kq;
            uint32_t a0 = arow0[kof];
            uint32_t a1 = arow1[kof];
            uint32_t a2 = arow0[kof + 4];
            uint32_t a3 = arow1[kof + 4];
            const uint4* b0p = (const uint4*)(Bb + kof*BSTP + rr*NT);
            const uint4* b1p = (const uint4*)(Bb + (kof+4)*BSTP + rr*NT);
            #pragma unroll
            for (int ng = 0; ng < NT/4; ng++) {
                uint4 b0 = b0p[ng];
                uint4 b1 = b1p[ng];
                mma_tf32(acc[ng*4+0], a0,a1,a2,a3, b0.x, b1.x);
                mma_tf32(acc[ng*4+1], a0,a1,a2,a3, b0.y, b1.y);
                mma_tf32(acc[ng*4+2], a0,a1,a2,a3, b0.z, b1.z);
                mma_tf32(acc[ng*4+3], a0,a1,a2,a3, b0.w, b1.w);
            }
        }
    }

    // ---- epilogue: bias + mish, scale, half2 stores ----
    const int px0 = wid*16 + rr;
    const int px1 = px0 + 8;
    const int y0 = ty + (px0 >> 3), x0c = tx + (px0 & 7);
    const int y1 = ty + (px1 >> 3), x1c = tx + (px1 & 7);
    __half* op0 = out + (size_t)((b*HH + y0)*WW + x0c)*COUT;
    __half* op1 = out + (size_t)((b*HH + y1)*WW + x1c)*COUT;

    #pragma unroll
    for (int nt = 0; nt < NT; nt++) {
        int ch = nt*8 + kq*2;
        float bb0 = sbias[ch], bb1 = sbias[ch+1];
        *(__half2*)(op0 + ch) = __floats2half2_rn(mish_f(acc[nt][0] + bb0) * oscale,
                                                  mish_f(acc[nt][1] + bb1) * oscale);
        *(__half2*)(op1 + ch) = __floats2half2_rn(mish_f(acc[nt][2] + bb0) * oscale,
                                                  mish_f(acc[nt][3] + bb1) * oscale);
    }
}

// ================= final flow head (32 -> 2, half in, float out) =================
__global__ void layer5_kernel(const __half* __restrict__ in,
                              const float* __restrict__ dww,
                              const float* __restrict__ pw,
                              float* __restrict__ out, float iscale)
{
    __shared__ __align__(16) float halo[180*36];
    __shared__ __align__(16) float wsm[288 + 64];

    const int b  = blockIdx.z;
    const int ty = blockIdx.y * 16;
    const int tx = blockIdx.x * 8;
    const int tid = threadIdx.x;

    for (int j = tid; j < 288; j += 128) wsm[j] = dww[j] * iscale;
    if (tid < 64) wsm[288 + tid] = pw[tid];

    for (int idx = tid; idx < 720; idx += 128) {
        int g8 = idx & 3, p = idx >> 2;
        int hy = p / 10, hx = p - hy*10;
        int gy = ty - 1 + hy, gx = tx - 1 + hx;
        uint4 v = make_uint4(0u,0u,0u,0u);
        if (gy >= 0 && gy < HH && gx >= 0 && gx < WW)
            v = ((const uint4*)in)[(size_t)((b*HH+gy)*WW+gx)*4 + g8];
        __half2* hp = (__half2*)&v;
        float2 f0 = __half22float2(hp[0]), f1 = __half22float2(hp[1]);
        float2 f2 = __half22float2(hp[2]), f3 = __half22float2(hp[3]);
        *(float4*)(halo + p*36 + g8*8)     = make_float4(f0.x, f0.y, f1.x, f1.y);
        *(float4*)(halo + p*36 + g8*8 + 4) = make_float4(f2.x, f2.y, f3.x, f3.y);
    }
    __syncthreads();

    int y = tid >> 3, x = tid & 7;
    float dwv[32];
    #pragma unroll
    for (int c = 0; c < 32; c++) dwv[c] = 0.f;

    #pragma unroll
    for (int t = 0; t < 9; t++) {
        int hp = ((y + t/3)*10 + (x + t%3))*36;
        #pragma unroll
        for (int c4 = 0; c4 < 8; c4++) {
            float4 h = *(const float4*)(halo + hp + c4*4);
            float4 w = *(const float4*)(wsm + t*32 + c4*4);
            dwv[c4*4+0] = fmaf(w.x, h.x, dwv[c4*4+0]);
            dwv[c4*4+1] = fmaf(w.y, h.y, dwv[c4*4+1]);
            dwv[c4*4+2] = fmaf(w.z, h.z, dwv[c4*4+2]);
            dwv[c4*4+3] = fmaf(w.w, h.w, dwv[c4*4+3]);
        }
    }

    float o0 = 0.f, o1 = 0.f;
    #pragma unroll
    for (int c = 0; c < 32; c++) {
        o0 = fmaf(dwv[c], wsm[288 + c*2 + 0], o0);
        o1 = fmaf(dwv[c], wsm[288 + c*2 + 1], o1);
    }
    int pix = (b*HH + ty + y)*WW + tx + x;
    float2 r; r.x = o0; r.y = o1;
    *(float2*)(out + (size_t)pix*2) = r;
}

// ================= host launch =================
extern "C" void kernel_launch(void* const* d_in, const int* in_sizes, int n_in,
                              void* d_out, int out_size)
{
    const float* prv = (const float*)d_in[0];
    const float* nxt = (const float*)d_in[1];
    const float* dw0 = (const float*)d_in[2];
    const float* pw0 = (const float*)d_in[3];
    const float* b0  = (const float*)d_in[4];
    const float* dw1 = (const float*)d_in[5];
    const float* pw1 = (const float*)d_in[6];
    const float* b1  = (const float*)d_in[7];
    const float* dw2 = (const float*)d_in[8];
    const float* pw2 = (const float*)d_in[9];
    const float* b2  = (const float*)d_in[10];
    const float* dw3 = (const float*)d_in[11];
    const float* pw3 = (const float*)d_in[12];
    const float* b3  = (const float*)d_in[13];
    const float* dw4 = (const float*)d_in[14];
    const float* pw4 = (const float*)d_in[15];
    const float* b4  = (const float*)d_in[16];
    const float* dw5 = (const float*)d_in[17];
    const float* pw5 = (const float*)d_in[18];
    float* out = (float*)d_out;

    float *cost; __half *bufA, *bufB;
    cudaGetSymbolAddress((void**)&cost, g_cost);
    cudaGetSymbolAddress((void**)&bufA, g_bufA);
    cudaGetSymbolAddress((void**)&bufB, g_bufB);

    const float S0 = 8.f, S1 = 128.f, S2 = 2048.f, S3 = 32768.f, S4 = 524288.f;

    const int SC = 24*CRS*4;
    // smem bytes: 2816 + 2*HBYT + 18432 + 2*32*BSTP*4
    const int SL0 = 2816 + 46080 + 18432 + 33792;  // 101120 (fp32 halo, NT16)
    const int SL1 = 2816 + 28800 + 18432 + 33792;  // 83840  (fp16, NT16)
    const int SL2 = 2816 + 28800 + 18432 + 25600;  // 75648  (fp16, NT12)
    const int SL3 = 2816 + 28800 + 18432 + 17408;  // 67456  (fp16, NT8)
    const int SL4 = 2816 + 28800 + 18432 + 9216;   // 59264  (fp16, NT4)

    cudaFuncSetAttribute(cost_kernel, cudaFuncAttributeMaxDynamicSharedMemorySize, SC);
    cudaFuncSetAttribute((const void*)layer_mma<337,352,128,true ,false>, cudaFuncAttributeMaxDynamicSharedMemorySize, SL0);
    cudaFuncSetAttribute((const void*)layer_mma<128,128,128,false,true >, cudaFuncAttributeMaxDynamicSharedMemorySize, SL1);
    cudaFuncSetAttribute((const void*)layer_mma<128,128, 96,false,true >, cudaFuncAttributeMaxDynamicSharedMemorySize, SL2);
    cudaFuncSetAttribute((const void*)layer_mma< 96, 96, 64,false,true >, cudaFuncAttributeMaxDynamicSharedMemorySize, SL3);
    cudaFuncSetAttribute((const void*)layer_mma< 64, 64, 32,false,true >, cudaFuncAttributeMaxDynamicSharedMemorySize, SL4);

    dim3 cgrid(16, 8, BATCH);
    cost_kernel<<<cgrid, 288, SC>>>(prv, nxt, cost);

    dim3 lgrid(16, 8, BATCH);
    layer_mma<337,352,128,true ,false><<<lgrid, 256, SL0>>>(prv,  nxt, cost, dw0, pw0, b0, bufA, 1.0f,    S0);
    layer_mma<128,128,128,false,true ><<<lgrid, 256, SL1>>>(bufA, nullptr, nullptr, dw1, pw1, b1, bufB, 1.f/S0, S1);
    layer_mma<128,128, 96,false,true ><<<lgrid, 256, SL2>>>(bufB, nullptr, nullptr, dw2, pw2, b2, bufA, 1.f/S1, S2);
    layer_mma< 96, 96, 64,false,true ><<<lgrid, 256, SL3>>>(bufA, nullptr, nullptr, dw3, pw3, b3, bufB, 1.f/S2, S3);
    layer_mma< 64, 64, 32,false,true ><<<lgrid, 256, SL4>>>(bufB, nullptr, nullptr, dw4, pw4, b4, bufA, 1.f/S3, S4);

    layer5_kernel<<<lgrid, 128>>>(bufA, dw5, pw5, out, 1.f/S4);
}

// round 13
// speedup vs baseline: 1.0686x; 1.0409x over previous
#include <cuda_runtime.h>
#include <math.h>
#include <stdint.h>

#define HH 128
#define WW 128
#define BATCH 8
#define NPIX (BATCH*HH*WW)

__device__ float g_cost[(size_t)NPIX*96];
__device__ float g_bufA[(size_t)NPIX*128];
__device__ float g_bufB[(size_t)NPIX*128];

__device__ __forceinline__ float mish_f(float v) {
    if (v > 20.f) return v;
    float u = __expf(v);
    float w = u * (u + 2.f);
    return v * __fdividef(w, w + 2.f);
}

__device__ __forceinline__ uint32_t f2tf32(float x) {
    uint32_t r;
    asm("cvt.rna.tf32.f32 %0, %1;" : "=r"(r) : "f"(x));
    return r;
}

__device__ __forceinline__ void mma_tf32(float acc[4],
                                         uint32_t a0, uint32_t a1, uint32_t a2, uint32_t a3,
                                         uint32_t b0, uint32_t b1) {
    asm volatile(
        "mma.sync.aligned.m16n8k8.row.col.f32.tf32.tf32.f32 "
        "{%0,%1,%2,%3}, {%4,%5,%6,%7}, {%8,%9}, {%0,%1,%2,%3};"
        : "+f"(acc[0]), "+f"(acc[1]), "+f"(acc[2]), "+f"(acc[3])
        : "r"(a0), "r"(a1), "r"(a2), "r"(a3), "r"(b0), "r"(b1));
}

// ================= cost volume =================
#define CCS 36
#define CRS 580
__global__ void __launch_bounds__(288, 2)
cost_kernel(const float* __restrict__ prv, const float* __restrict__ nxt,
            float* __restrict__ cost)
{
    extern __shared__ __align__(16) float sm[];
    const int b  = blockIdx.z;
    const int y0 = blockIdx.y * 16;
    const int xb = blockIdx.x * 8;
    const int tid = threadIdx.x;
    const int r  = tid / 18;
    const int q  = (tid % 18) / 9;
    const int di = tid % 9;
    const int xs = q * 4;

    float acc[36];
    #pragma unroll
    for (int k = 0; k < 36; k++) acc[k] = 0.f;

    for (int cc = 0; cc < 4; cc++) {
        if (cc) __syncthreads();
        for (int idx = tid; idx < 3072; idx += 288) {
            int c4 = idx & 7, col = (idx >> 3) & 15, row = idx >> 7;
            int gy = y0 - 4 + row, gx = xb - 4 + col;
            float4 v = make_float4(0.f,0.f,0.f,0.f);
            if (gy >= 0 && gy < HH && gx >= 0 && gx < WW)
                v = ((const float4*)nxt)[((b*HH+gy)*WW+gx)*32 + cc*8 + c4];
            *(float4*)(sm + row*CRS + col*CCS + c4*4) = v;
        }
        __syncthreads();

        const float* nbase = sm + (r + di)*CRS + xs*CCS;
        const float4* prow = (const float4*)prv + (size_t)((b*HH + y0 + r)*WW + xb + xs)*32 + cc*8;

        #pragma unroll 2
        for (int c4 = 0; c4 < 8; c4++) {
            float4 nv[12];
            #pragma unroll
            for (int m = 0; m < 12; m++)
                nv[m] = *(const float4*)(nbase + m*CCS + c4*4);
            #pragma unroll
            for (int i = 0; i < 4; i++) {
                float4 p = prow[i*32 + c4];
                #pragma unroll
                for (int dj = 0; dj < 9; dj++) {
                    float4 nn = nv[i + dj];
                    float s = acc[i*9+dj];
                    s = fmaf(p.x, nn.x, s); s = fmaf(p.y, nn.y, s);
                    s = fmaf(p.z, nn.z, s); s = fmaf(p.w, nn.w, s);
                    acc[i*9+dj] = s;
                }
            }
        }
    }

    const float inv = 1.0f / 128.0f;
    #pragma unroll
    for (int i = 0; i < 4; i++) {
        size_t base = (size_t)((b*HH + y0 + r)*WW + xb + xs + i)*96 + di*9;
        #pragma unroll
        for (int dj = 0; dj < 9; dj++)
            cost[base + dj] = acc[i*9+dj] * inv;
    }
}

// ================= fused sep-conv layer (mma.sync tf32, warp-pipelined, fp32) =================
// ONE block barrier per chunk; depthwise->MMA handoff is __syncwarp (warp w writes
// exactly the dwt rows its MMA reads). sdw double-buffered; halo prefetch for kc+1
// issued after depthwise(kc) into the other halo buffer.
template<int CIN, int CINB, int COUT, bool L0M>
__global__ void __launch_bounds__(256, 2)
layer_mma(const float* __restrict__ in, const float* __restrict__ in2,
          const float* __restrict__ inc, const float* __restrict__ dww,
          const float* __restrict__ pw, const float* __restrict__ bias,
          float* __restrict__ out)
{
    constexpr int KCH  = CINB / 32;
    constexpr int NT   = COUT / 8;
    constexpr int BSTP = 8*NT + 4;
    constexpr int BBUF = 32 * BSTP;

    extern __shared__ __align__(16) float smf[];
    char*     smc   = (char*)smf;
    float*    sdw   = smf;                          // 2 x 288
    float*    sbias = smf + 576;                    // 128 (+pad to 704)
    float*    halo  = smf + 704;                    // byte 2816, 2 x 5760 floats
    uint32_t* dwt   = (uint32_t*)(smc + 2816 + 46080);          // 128*36 words
    uint32_t* Bsm   = (uint32_t*)(smc + 2816 + 46080 + 18432);  // 2*BBUF

    const int b  = blockIdx.z;
    const int ty = blockIdx.y * 16;
    const int tx = blockIdx.x * 8;
    const int tid = threadIdx.x;
    const int lane = tid & 31;
    const int wid  = tid >> 5;
    const int kq  = lane & 3;
    const int rr  = lane >> 2;
    const int pc4 = tid & 7;

    if (tid < COUT) sbias[tid] = bias[tid];

    // ---- hoisted halo prefetch geometry ----
    int      hoff[6];
    int      hsz [6];
    uint32_t hdst[6];
    const uint32_t halo_sa = (uint32_t)__cvta_generic_to_shared(halo);
    #pragma unroll
    for (int s = 0; s < 6; s++) {
        int idx = tid + s*256;
        int p = idx >> 3;
        int hy = p / 10, hx = p - hy*10;
        int gy = ty - 1 + hy, gx = tx - 1 + hx;
        bool v = (idx < 1440) && gy >= 0 && gy < HH && gx >= 0 && gx < WW;
        int gyc = min(max(gy, 0), HH-1), gxc = min(max(gx, 0), WW-1);
        hoff[s] = (b*HH + gyc)*WW + gxc;
        hsz [s] = v ? 16 : 0;
        hdst[s] = halo_sa + (uint32_t)p*128 + (uint32_t)pc4*16;
    }

    auto issue_prefetch = [&](int kn, uint32_t bufb) {
        const float4* src; int cof, strd;
        if constexpr (L0M) {
            if (kn < 4)      { src = (const float4*)in;  cof = kn*8;     strd = 32; }
            else if (kn < 8) { src = (const float4*)in2; cof = (kn-4)*8; strd = 32; }
            else             { src = (const float4*)inc; cof = (kn-8)*8; strd = 24; }
        } else {
            src = (const float4*)in; cof = kn*8; strd = CINB/4;
        }
        #pragma unroll
        for (int s = 0; s < 6; s++) {
            if (tid + s*256 < 1440) {
                const void* p = (const void*)(src + (size_t)hoff[s]*strd + cof + pc4);
                asm volatile("cp.async.cg.shared.global [%0], [%1], 16, %2;"
                             :: "r"(hdst[s] + bufb), "l"(p), "r"(hsz[s]) : "memory");
            }
        }
        asm volatile("cp.async.commit_group;" ::: "memory");
    };

    float acc[NT][4];
    #pragma unroll
    for (int n = 0; n < NT; n++)
        #pragma unroll
        for (int j = 0; j < 4; j++) acc[n][j] = 0.f;

    issue_prefetch(0, 0);

    const int dr  = tid >> 4;
    const int dxh = ((tid >> 3) & 1) * 4;

    for (int kc = 0; kc < KCH; kc++) {
        const int k0 = kc * 32;
        uint32_t* Bb = Bsm + (kc & 1) * BBUF;
        float* sdwb  = sdw + (kc & 1) * 288;

        // ---- B chunk [32][COUT] -> permuted tf32 smem ----
        #pragma unroll
        for (int s = 0; s < COUT/8; s++) {
            int j = tid + s*256;
            int kk = j / COUT, co = j - kk*COUT;
            int cb = k0 + kk;
            int corig = L0M ? (cb < 256 ? cb + 81 : cb - 256) : cb;
            bool valid = L0M ? (cb < 337) : true;
            float w = valid ? pw[(size_t)corig*COUT + co] : 0.f;
            Bb[kk*BSTP + (co & 7)*NT + (co >> 3)] = f2tf32(w);
        }
        // ---- depthwise weights chunk [9][32] (double-buffered) ----
        #pragma unroll
        for (int s = 0; s < 2; s++) {
            int j = tid + s*256;
            if (j < 288) {
                int t = j >> 5, c = j & 31;
                int cb = k0 + c;
                int corig = L0M ? (cb < 256 ? cb + 81 : cb - 256) : cb;
                bool valid = L0M ? (cb < 337) : true;
                sdwb[j] = valid ? dww[t*CIN + corig] : 0.f;
            }
        }
        asm volatile("cp.async.wait_group 0;" ::: "memory");
        __syncthreads();   // [A] the ONLY block barrier per chunk

        // ---- depthwise 3x3: 4 adjacent px, one c4 quad, row-window reuse ----
        {
            const float* hb = halo + (kc & 1) * 5760;
            float4 o0 = make_float4(0.f,0.f,0.f,0.f);
            float4 o1 = o0, o2 = o0, o3 = o0;
            #pragma unroll
            for (int tyy = 0; tyy < 3; tyy++) {
                const float* hr = hb + ((dr + tyy)*10 + dxh)*32 + pc4*4;
                float4 h0 = *(const float4*)(hr + 0*32);
                float4 h1 = *(const float4*)(hr + 1*32);
                float4 h2 = *(const float4*)(hr + 2*32);
                float4 h3 = *(const float4*)(hr + 3*32);
                float4 h4 = *(const float4*)(hr + 4*32);
                float4 h5 = *(const float4*)(hr + 5*32);
                float4 w0 = *(const float4*)(sdwb + (tyy*3+0)*32 + pc4*4);
                float4 w1 = *(const float4*)(sdwb + (tyy*3+1)*32 + pc4*4);
                float4 w2 = *(const float4*)(sdwb + (tyy*3+2)*32 + pc4*4);
                #define DWACC(o, a, b, c) \
                    o.x = fmaf(w0.x, a.x, o.x); o.y = fmaf(w0.y, a.y, o.y); \
                    o.z = fmaf(w0.z, a.z, o.z); o.w = fmaf(w0.w, a.w, o.w); \
                    o.x = fmaf(w1.x, b.x, o.x); o.y = fmaf(w1.y, b.y, o.y); \
                    o.z = fmaf(w1.z, b.z, o.z); o.w = fmaf(w1.w, b.w, o.w); \
                    o.x = fmaf(w2.x, c.x, o.x); o.y = fmaf(w2.y, c.y, o.y); \
                    o.z = fmaf(w2.z, c.z, o.z); o.w = fmaf(w2.w, c.w, o.w);
                DWACC(o0, h0, h1, h2)
                DWACC(o1, h1, h2, h3)
                DWACC(o2, h2, h3, h4)
                DWACC(o3, h3, h4, h5)
                #undef DWACC
            }
            const int pxb = dr*8 + dxh;
            uint4 t0, t1, t2, t3;
            t0.x=f2tf32(o0.x); t0.y=f2tf32(o0.y); t0.z=f2tf32(o0.z); t0.w=f2tf32(o0.w);
            t1.x=f2tf32(o1.x); t1.y=f2tf32(o1.y); t1.z=f2tf32(o1.z); t1.w=f2tf32(o1.w);
            t2.x=f2tf32(o2.x); t2.y=f2tf32(o2.y); t2.z=f2tf32(o2.z); t2.w=f2tf32(o2.w);
            t3.x=f2tf32(o3.x); t3.y=f2tf32(o3.y); t3.z=f2tf32(o3.z); t3.w=f2tf32(o3.w);
            *(uint4*)(dwt + (pxb+0)*36 + pc4*4) = t0;
            *(uint4*)(dwt + (pxb+1)*36 + pc4*4) = t1;
            *(uint4*)(dwt + (pxb+2)*36 + pc4*4) = t2;
            *(uint4*)(dwt + (pxb+3)*36 + pc4*4) = t3;
        }

        // ---- prefetch halo for kc+1 (other buffer; stragglers read kc's buffer) ----
        if (kc + 1 < KCH)
            issue_prefetch(kc + 1, (uint32_t)(((kc + 1) & 1) * 23040));

        __syncwarp();      // [B] intra-warp handoff: dwt rows 16w..16w+15

        // ---- MMA: 4 k-blocks of 8, B fragments via LDS.128 ----
        const uint32_t* arow0 = dwt + (wid*16 + rr)*36;
        const uint32_t* arow1 = arow0 + 8*36;
        #pragma unroll
        for (int kb = 0; kb < 4; kb++) {
            const int kof = kb*8 + kq;
            uint32_t a0 = arow0[kof];
            uint32_t a1 = arow1[kof];
            uint32_t a2 = arow0[kof + 4];
            uint32_t a3 = arow1[kof + 4];
            const uint4* b0p = (const uint4*)(Bb + kof*BSTP + rr*NT);
            const uint4* b1p = (const uint4*)(Bb + (kof+4)*BSTP + rr*NT);
            #pragma unroll
            for (int ng = 0; ng < NT/4; ng++) {
                uint4 b0 = b0p[ng];
                uint4 b1 = b1p[ng];
                mma_tf32(acc[ng*4+0], a0,a1,a2,a3, b0.x, b1.x);
                mma_tf32(acc[ng*4+1], a0,a1,a2,a3, b0.y, b1.y);
                mma_tf32(acc[ng*4+2], a0,a1,a2,a3, b0.z, b1.z);
                mma_tf32(acc[ng*4+3], a0,a1,a2,a3, b0.w, b1.w);
            }
        }
    }

    // ---- epilogue: bias + mish, float2 stores ----
    const int px0 = wid*16 + rr;
    const int px1 = px0 + 8;
    const int y0 = ty + (px0 >> 3), x0c = tx + (px0 & 7);
    const int y1 = ty + (px1 >> 3), x1c = tx + (px1 & 7);
    float* op0 = out + (size_t)((b*HH + y0)*WW + x0c)*COUT;
    float* op1 = out + (size_t)((b*HH + y1)*WW + x1c)*COUT;

    #pragma unroll
    for (int nt = 0; nt < NT; nt++) {
        int ch = nt*8 + kq*2;
        float bb0 = sbias[ch], bb1 = sbias[ch+1];
        float2 r0, r1;
        r0.x = mish_f(acc[nt][0] + bb0);
        r0.y = mish_f(acc[nt][1] + bb1);
        r1.x = mish_f(acc[nt][2] + bb0);
        r1.y = mish_f(acc[nt][3] + bb1);
        *(float2*)(op0 + ch) = r0;
        *(float2*)(op1 + ch) = r1;
    }
}

// ================= final flow head (32 -> 2) =================
__global__ void layer5_kernel(const float* __restrict__ in,
                              const float* __restrict__ dww,
                              const float* __restrict__ pw,
                              float* __restrict__ out)
{
    __shared__ __align__(16) float halo[180*36];
    __shared__ __align__(16) float wsm[288 + 64];

    const int b  = blockIdx.z;
    const int ty = blockIdx.y * 16;
    const int tx = blockIdx.x * 8;
    const int tid = threadIdx.x;

    for (int j = tid; j < 288; j += 128) wsm[j] = dww[j];
    if (tid < 64) wsm[288 + tid] = pw[tid];

    for (int idx = tid; idx < 1440; idx += 128) {
        int c4 = idx & 7, p = idx >> 3;
        int hy = p / 10, hx = p - hy*10;
        int gy = ty - 1 + hy, gx = tx - 1 + hx;
        float4 v = make_float4(0.f,0.f,0.f,0.f);
        if (gy >= 0 && gy < HH && gx >= 0 && gx < WW)
            v = ((const float4*)in)[(size_t)((b*HH+gy)*WW+gx)*8 + c4];
        *(float4*)(halo + p*36 + c4*4) = v;
    }
    __syncthreads();

    int y = tid >> 3, x = tid & 7;
    float dwv[32];
    #pragma unroll
    for (int c = 0; c < 32; c++) dwv[c] = 0.f;

    #pragma unroll
    for (int t = 0; t < 9; t++) {
        int hp = ((y + t/3)*10 + (x + t%3))*36;
        #pragma unroll
        for (int c4 = 0; c4 < 8; c4++) {
            float4 h = *(const float4*)(halo + hp + c4*4);
            float4 w = *(const float4*)(wsm + t*32 + c4*4);
            dwv[c4*4+0] = fmaf(w.x, h.x, dwv[c4*4+0]);
            dwv[c4*4+1] = fmaf(w.y, h.y, dwv[c4*4+1]);
            dwv[c4*4+2] = fmaf(w.z, h.z, dwv[c4*4+2]);
            dwv[c4*4+3] = fmaf(w.w, h.w, dwv[c4*4+3]);
        }
    }

    float o0 = 0.f, o1 = 0.f;
    #pragma unroll
    for (int c = 0; c < 32; c++) {
        o0 = fmaf(dwv[c], wsm[288 + c*2 + 0], o0);
        o1 = fmaf(dwv[c], wsm[288 + c*2 + 1], o1);
    }
    int pix = (b*HH + ty + y)*WW + tx + x;
    float2 r; r.x = o0; r.y = o1;
    *(float2*)(out + (size_t)pix*2) = r;
}

// ================= host launch =================
extern "C" void kernel_launch(void* const* d_in, const int* in_sizes, int n_in,
                              void* d_out, int out_size)
{
    const float* prv = (const float*)d_in[0];
    const float* nxt = (const float*)d_in[1];
    const float* dw0 = (const float*)d_in[2];
    const float* pw0 = (const float*)d_in[3];
    const float* b0  = (const float*)d_in[4];
    const float* dw1 = (const float*)d_in[5];
    const float* pw1 = (const float*)d_in[6];
    const float* b1  = (const float*)d_in[7];
    const float* dw2 = (const float*)d_in[8];
    const float* pw2 = (const float*)d_in[9];
    const float* b2  = (const float*)d_in[10];
    const float* dw3 = (const float*)d_in[11];
    const float* pw3 = (const float*)d_in[12];
    const float* b3  = (const float*)d_in[13];
    const float* dw4 = (const float*)d_in[14];
    const float* pw4 = (const float*)d_in[15];
    const float* b4  = (const float*)d_in[16];
    const float* dw5 = (const float*)d_in[17];
    const float* pw5 = (const float*)d_in[18];
    float* out = (float*)d_out;

    float *cost, *bufA, *bufB;
    cudaGetSymbolAddress((void**)&cost, g_cost);
    cudaGetSymbolAddress((void**)&bufA, g_bufA);
    cudaGetSymbolAddress((void**)&bufB, g_bufB);

    const int SC = 24*CRS*4;
    // smem bytes: 2816 + 46080 + 18432 + 2*32*BSTP*4
    const int SL128 = 2816 + 46080 + 18432 + 33792;  // 101120 (NT16)
    const int SL96  = 2816 + 46080 + 18432 + 25600;  // 92928  (NT12)
    const int SL64  = 2816 + 46080 + 18432 + 17408;  // 84736  (NT8)
    const int SL32  = 2816 + 46080 + 18432 + 9216;   // 76544  (NT4)

    cudaFuncSetAttribute(cost_kernel, cudaFuncAttributeMaxDynamicSharedMemorySize, SC);
    cudaFuncSetAttribute((const void*)layer_mma<337,352,128,true >, cudaFuncAttributeMaxDynamicSharedMemorySize, SL128);
    cudaFuncSetAttribute((const void*)layer_mma<128,128,128,false>, cudaFuncAttributeMaxDynamicSharedMemorySize, SL128);
    cudaFuncSetAttribute((const void*)layer_mma<128,128, 96,false>, cudaFuncAttributeMaxDynamicSharedMemorySize, SL96);
    cudaFuncSetAttribute((const void*)layer_mma< 96, 96, 64,false>, cudaFuncAttributeMaxDynamicSharedMemorySize, SL64);
    cudaFuncSetAttribute((const void*)layer_mma< 64, 64, 32,false>, cudaFuncAttributeMaxDynamicSharedMemorySize, SL32);

    dim3 cgrid(16, 8, BATCH);
    cost_kernel<<<cgrid, 288, SC>>>(prv, nxt, cost);

    dim3 lgrid(16, 8, BATCH);
    layer_mma<337,352,128,true ><<<lgrid, 256, SL128>>>(prv,  nxt, cost, dw0, pw0, b0, bufA);
    layer_mma<128,128,128,false><<<lgrid, 256, SL128>>>(bufA, nullptr, nullptr, dw1, pw1, b1, bufB);
    layer_mma<128,128, 96,false><<<lgrid, 256, SL96 >>>(bufB, nullptr, nullptr, dw2, pw2, b2, bufA);
    layer_mma< 96, 96, 64,false><<<lgrid, 256, SL64 >>>(bufA, nullptr, nullptr, dw3, pw3, b3, bufB);
    layer_mma< 64, 64, 32,false><<<lgrid, 256, SL32 >>>(bufB, nullptr, nullptr, dw4, pw4, b4, bufA);

    layer5_kernel<<<lgrid, 128>>>(bufA, dw5, pw5, out);
}